// round 1
// baseline (speedup 1.0000x reference)
#include <cuda_runtime.h>
#include <cuda_bf16.h>
#include <math.h>
#include <stdint.h>

using bf16 = __nv_bfloat16;

#define NB   32
#define SR   2048
#define SP   2048
#define DIN  400
#define HID  512

// ---------------- scratch (device globals; no runtime alloc) ----------------
__device__ bf16  g_q[(size_t)NB*SR*HID];   // 67 MB
__device__ bf16  g_k[(size_t)NB*SP*HID];
__device__ bf16  g_v[(size_t)NB*SP*HID];
__device__ bf16  g_o[(size_t)NB*SR*HID];
__device__ float g_x[(size_t)NB*SR*DIN];   // 105 MB

// ---------------- mma helper: m16n8k16 row.col bf16 -> f32 ----------------
__device__ __forceinline__ void mma16816(float c[4], const uint32_t a[4], const uint32_t b[2]) {
    asm volatile(
        "mma.sync.aligned.m16n8k16.row.col.f32.bf16.bf16.f32 "
        "{%0,%1,%2,%3}, {%4,%5,%6,%7}, {%8,%9}, {%0,%1,%2,%3};\n"
        : "+f"(c[0]), "+f"(c[1]), "+f"(c[2]), "+f"(c[3])
        : "r"(a[0]), "r"(a[1]), "r"(a[2]), "r"(a[3]), "r"(b[0]), "r"(b[1]));
}

// 4-element load+convert helpers (overloaded on source type)
__device__ __forceinline__ void ldcvt4(const float* p, bf16* h) {
    float4 f = *(const float4*)p;
    h[0] = __float2bfloat16(f.x); h[1] = __float2bfloat16(f.y);
    h[2] = __float2bfloat16(f.z); h[3] = __float2bfloat16(f.w);
}
__device__ __forceinline__ void ldcvt4(const bf16* p, bf16* h) {
    *(uint2*)h = *(const uint2*)p;
}

// ---------------- generic GEMM:  C[M,N] = A[M,K] * W[K,N] + bias ----------------
// MODE 0: store bf16 C            MODE 1: store fp32  R + gate*C
template<typename AT, int MODE>
__global__ __launch_bounds__(256) void gemm_kernel(
    const AT* __restrict__ A, const float* __restrict__ W,
    const float* __restrict__ bias, const float* __restrict__ R,
    const float* __restrict__ gatep, void* __restrict__ outp,
    int M, int N, int K)
{
    constexpr int BM = 128, BN = 64, BK = 32, SA = 40, SB = 40;
    __shared__ __align__(16) bf16 As[BM * SA];
    __shared__ __align__(16) bf16 Bs[BN * SB];

    const int tid  = threadIdx.x;
    const int warp = tid >> 5, lane = tid & 31;
    const int wm = warp >> 1, wn = warp & 1;         // 4x2 warp grid, 32x32 per warp
    const int m0 = blockIdx.y * BM, n0 = blockIdx.x * BN;

    float c[2][4][4];
    #pragma unroll
    for (int i = 0; i < 2; i++)
        #pragma unroll
        for (int j = 0; j < 4; j++)
            #pragma unroll
            for (int t = 0; t < 4; t++) c[i][j][t] = 0.f;

    for (int k0 = 0; k0 < K; k0 += BK) {
        // --- A tile: 128x32, converted to bf16 ---
        {
            const int kq = tid & 7;          // col group (4 elems)
            const int r0 = tid >> 3;         // 0..31
            const int gk = k0 + 4 * kq;
            #pragma unroll
            for (int rr = 0; rr < 4; rr++) {
                const int r = r0 + rr * 32;
                __align__(8) bf16 h[4];
                if (gk < K) ldcvt4(A + (size_t)(m0 + r) * K + gk, h);
                else { h[0]=h[1]=h[2]=h[3]=__float2bfloat16(0.f); }
                *(uint2*)&As[r * SA + 4 * kq] = *(uint2*)h;
            }
        }
        // --- W tile: 32x64, transposed into Bs[n][k] ---
        {
            const int cq = tid & 15;         // col group (4 elems)
            const int r0 = tid >> 4;         // 0..15
            #pragma unroll
            for (int rr = 0; rr < 2; rr++) {
                const int r  = r0 + rr * 16;
                const int gk = k0 + r;
                const int gn = n0 + 4 * cq;
                float4 f = make_float4(0.f, 0.f, 0.f, 0.f);
                if (gk < K && gn < N) f = *(const float4*)(W + (size_t)gk * N + gn);
                Bs[(4*cq+0) * SB + r] = __float2bfloat16(f.x);
                Bs[(4*cq+1) * SB + r] = __float2bfloat16(f.y);
                Bs[(4*cq+2) * SB + r] = __float2bfloat16(f.z);
                Bs[(4*cq+3) * SB + r] = __float2bfloat16(f.w);
            }
        }
        __syncthreads();
        #pragma unroll
        for (int kk = 0; kk < BK; kk += 16) {
            uint32_t a[2][4];
            #pragma unroll
            for (int mi = 0; mi < 2; mi++) {
                const int mrow = wm * 32 + mi * 16 + (lane >> 2);
                const int kcol = kk + 2 * (lane & 3);
                a[mi][0] = *(const uint32_t*)&As[ mrow      * SA + kcol    ];
                a[mi][1] = *(const uint32_t*)&As[(mrow + 8) * SA + kcol    ];
                a[mi][2] = *(const uint32_t*)&As[ mrow      * SA + kcol + 8];
                a[mi][3] = *(const uint32_t*)&As[(mrow + 8) * SA + kcol + 8];
            }
            #pragma unroll
            for (int nj = 0; nj < 4; nj++) {
                const int nrow = wn * 32 + nj * 8 + (lane >> 2);
                uint32_t b[2];
                b[0] = *(const uint32_t*)&Bs[nrow * SB + kk + 2 * (lane & 3)    ];
                b[1] = *(const uint32_t*)&Bs[nrow * SB + kk + 2 * (lane & 3) + 8];
                #pragma unroll
                for (int mi = 0; mi < 2; mi++) mma16816(c[mi][nj], a[mi], b);
            }
        }
        __syncthreads();
    }

    // --- epilogue ---
    float gate = 0.f;
    if (MODE == 1) gate = *gatep;
    #pragma unroll
    for (int mi = 0; mi < 2; mi++) {
        const int r = m0 + wm * 32 + mi * 16 + (lane >> 2);
        #pragma unroll
        for (int nj = 0; nj < 4; nj++) {
            const int cn = n0 + wn * 32 + nj * 8 + 2 * (lane & 3);
            if (cn < N) {
                const float b0 = bias[cn], b1 = bias[cn + 1];
                const float v0 = c[mi][nj][0] + b0, v1 = c[mi][nj][1] + b1;
                const float v2 = c[mi][nj][2] + b0, v3 = c[mi][nj][3] + b1;
                if (MODE == 0) {
                    bf16* out = (bf16*)outp;
                    __nv_bfloat162 p0; p0.x = __float2bfloat16(v0); p0.y = __float2bfloat16(v1);
                    __nv_bfloat162 p1; p1.x = __float2bfloat16(v2); p1.y = __float2bfloat16(v3);
                    *(__nv_bfloat162*)&out[(size_t)r * N + cn]       = p0;
                    *(__nv_bfloat162*)&out[(size_t)(r + 8) * N + cn] = p1;
                } else {
                    float* out = (float*)outp;
                    const size_t i0 = (size_t)r * N + cn;
                    const size_t i1 = (size_t)(r + 8) * N + cn;
                    out[i0]     = R[i0]     + gate * v0;
                    out[i0 + 1] = R[i0 + 1] + gate * v1;
                    out[i1]     = R[i1]     + gate * v2;
                    out[i1 + 1] = R[i1 + 1] + gate * v3;
                }
            }
        }
    }
}

// ---------------- attention: per-block (batch, 64 q-rows), no-max softmax ----------------
// smem: Qs[64][520] bf16 | Ks[64][72] bf16 | Vs[512][72] bf16 (transposed) | Ps[64][72] bf16 | l[64] f32
#define QS_STRIDE 520
#define KS_STRIDE 72
#define SMEM_QS   0
#define SMEM_KS   66560
#define SMEM_VS   (66560 + 9216)
#define SMEM_PS   (66560 + 9216 + 73728)
#define SMEM_L    (66560 + 9216 + 73728 + 9216)
#define SMEM_ATTN (SMEM_L + 256)

__global__ __launch_bounds__(256, 1) void attn_kernel()
{
    extern __shared__ __align__(16) char sm[];
    bf16*  Qs = (bf16*)(sm + SMEM_QS);
    bf16*  Ks = (bf16*)(sm + SMEM_KS);
    bf16*  Vs = (bf16*)(sm + SMEM_VS);
    bf16*  Ps = (bf16*)(sm + SMEM_PS);
    float* l  = (float*)(sm + SMEM_L);

    const int tid = threadIdx.x, warp = tid >> 5, lane = tid & 31;
    const int b = blockIdx.y, q0 = blockIdx.x * 64;
    const bf16* Qg = g_q + ((size_t)b * SR + q0) * HID;
    const bf16* Kg = g_k + (size_t)b * SP * HID;
    const bf16* Vg = g_v + (size_t)b * SP * HID;

    // load Q tile 64x512 (resident)
    {
        const int hq = tid & 63;     // 8 halves each
        const int r0 = tid >> 6;     // 0..3
        #pragma unroll
        for (int rr = 0; rr < 16; rr++) {
            const int r = r0 + rr * 4;
            uint4 u = *(const uint4*)(Qg + (size_t)r * HID + 8 * hq);
            *(uint4*)&Qs[r * QS_STRIDE + 8 * hq] = u;
        }
    }
    if (tid < 64) l[tid] = 0.f;
    __syncthreads();

    const int wmS = warp >> 1, wnS = warp & 1;    // S-phase: 4x2 warp grid (16x32 tiles)
    const float scale = 0.044194173824159216f;    // 1/sqrt(512)

    float of[4][8][4];                            // O: warp owns [64 q][64 h], h-offset = warp*64
    #pragma unroll
    for (int i = 0; i < 4; i++)
        #pragma unroll
        for (int j = 0; j < 8; j++)
            #pragma unroll
            for (int t = 0; t < 4; t++) of[i][j][t] = 0.f;

    for (int kt = 0; kt < 32; kt++) {
        const int k0 = kt * 64;

        // ---- S = Q K^T (accumulate over H in 8 chunks of 64) ----
        float sc[4][4];
        #pragma unroll
        for (int j = 0; j < 4; j++)
            #pragma unroll
            for (int t = 0; t < 4; t++) sc[j][t] = 0.f;

        for (int hc = 0; hc < 8; hc++) {
            {   // load K chunk 64 rows x 64 h
                const int hq = tid & 7;
                const int r0 = tid >> 3;     // 0..31
                #pragma unroll
                for (int rr = 0; rr < 2; rr++) {
                    const int r = r0 + rr * 32;
                    uint4 u = *(const uint4*)(Kg + (size_t)(k0 + r) * HID + hc * 64 + 8 * hq);
                    *(uint4*)&Ks[r * KS_STRIDE + 8 * hq] = u;
                }
            }
            __syncthreads();
            #pragma unroll
            for (int kk = 0; kk < 64; kk += 16) {
                uint32_t a[4];
                const int mrow = wmS * 16 + (lane >> 2);
                const int kcol = hc * 64 + kk + 2 * (lane & 3);
                a[0] = *(const uint32_t*)&Qs[ mrow      * QS_STRIDE + kcol    ];
                a[1] = *(const uint32_t*)&Qs[(mrow + 8) * QS_STRIDE + kcol    ];
                a[2] = *(const uint32_t*)&Qs[ mrow      * QS_STRIDE + kcol + 8];
                a[3] = *(const uint32_t*)&Qs[(mrow + 8) * QS_STRIDE + kcol + 8];
                #pragma unroll
                for (int nj = 0; nj < 4; nj++) {
                    const int nrow = wnS * 32 + nj * 8 + (lane >> 2);
                    uint32_t bb[2];
                    bb[0] = *(const uint32_t*)&Ks[nrow * KS_STRIDE + kk + 2 * (lane & 3)    ];
                    bb[1] = *(const uint32_t*)&Ks[nrow * KS_STRIDE + kk + 2 * (lane & 3) + 8];
                    mma16816(sc[nj], a, bb);
                }
            }
            __syncthreads();
        }

        // ---- softmax numerator (no max subtraction; logits are O(1)) ----
        {
            const int r0 = wmS * 16 + (lane >> 2);
            float rs0 = 0.f, rs1 = 0.f;
            #pragma unroll
            for (int nj = 0; nj < 4; nj++) {
                const int n = wnS * 32 + nj * 8 + 2 * (lane & 3);
                const float e00 = __expf(sc[nj][0] * scale);
                const float e01 = __expf(sc[nj][1] * scale);
                const float e10 = __expf(sc[nj][2] * scale);
                const float e11 = __expf(sc[nj][3] * scale);
                rs0 += e00 + e01; rs1 += e10 + e11;
                __nv_bfloat162 p0; p0.x = __float2bfloat16(e00); p0.y = __float2bfloat16(e01);
                __nv_bfloat162 p1; p1.x = __float2bfloat16(e10); p1.y = __float2bfloat16(e11);
                *(__nv_bfloat162*)&Ps[ r0      * KS_STRIDE + n] = p0;
                *(__nv_bfloat162*)&Ps[(r0 + 8) * KS_STRIDE + n] = p1;
            }
            rs0 += __shfl_xor_sync(0xffffffffu, rs0, 1);
            rs0 += __shfl_xor_sync(0xffffffffu, rs0, 2);
            rs1 += __shfl_xor_sync(0xffffffffu, rs1, 1);
            rs1 += __shfl_xor_sync(0xffffffffu, rs1, 2);
            if ((lane & 3) == 0) { atomicAdd(&l[r0], rs0); atomicAdd(&l[r0 + 8], rs1); }
        }
        __syncthreads();

        // ---- load V tile transposed: Vs[h][krow] ----
        {
            const int hq = tid & 127;    // 4 halves each
            const int r0 = tid >> 7;     // 0..1
            #pragma unroll
            for (int rr = 0; rr < 32; rr++) {
                const int r = r0 + rr * 2;
                __align__(8) bf16 h[4];
                *(uint2*)h = *(const uint2*)(Vg + (size_t)(k0 + r) * HID + 4 * hq);
                Vs[(4*hq+0) * KS_STRIDE + r] = h[0];
                Vs[(4*hq+1) * KS_STRIDE + r] = h[1];
                Vs[(4*hq+2) * KS_STRIDE + r] = h[2];
                Vs[(4*hq+3) * KS_STRIDE + r] = h[3];
            }
        }
        __syncthreads();

        // ---- O += P V  (warp owns h-range warp*64..+64) ----
        #pragma unroll
        for (int kk = 0; kk < 64; kk += 16) {
            uint32_t a[4][4];
            #pragma unroll
            for (int mi = 0; mi < 4; mi++) {
                const int mrow = mi * 16 + (lane >> 2);
                const int kcol = kk + 2 * (lane & 3);
                a[mi][0] = *(const uint32_t*)&Ps[ mrow      * KS_STRIDE + kcol    ];
                a[mi][1] = *(const uint32_t*)&Ps[(mrow + 8) * KS_STRIDE + kcol    ];
                a[mi][2] = *(const uint32_t*)&Ps[ mrow      * KS_STRIDE + kcol + 8];
                a[mi][3] = *(const uint32_t*)&Ps[(mrow + 8) * KS_STRIDE + kcol + 8];
            }
            #pragma unroll
            for (int nj = 0; nj < 8; nj++) {
                const int nrow = warp * 64 + nj * 8 + (lane >> 2);
                uint32_t bb[2];
                bb[0] = *(const uint32_t*)&Vs[nrow * KS_STRIDE + kk + 2 * (lane & 3)    ];
                bb[1] = *(const uint32_t*)&Vs[nrow * KS_STRIDE + kk + 2 * (lane & 3) + 8];
                #pragma unroll
                for (int mi = 0; mi < 4; mi++) mma16816(of[mi][nj], a[mi], bb);
            }
        }
        __syncthreads();
    }

    // ---- normalize by l and store O (bf16) ----
    #pragma unroll
    for (int mi = 0; mi < 4; mi++) {
        const int r = mi * 16 + (lane >> 2);
        const float inv0 = 1.f / l[r];
        const float inv1 = 1.f / l[r + 8];
        #pragma unroll
        for (int nj = 0; nj < 8; nj++) {
            const int h = warp * 64 + nj * 8 + 2 * (lane & 3);
            const size_t base = ((size_t)b * SR + q0 + r) * HID + h;
            __nv_bfloat162 p0, p1;
            p0.x = __float2bfloat16(of[mi][nj][0] * inv0);
            p0.y = __float2bfloat16(of[mi][nj][1] * inv0);
            p1.x = __float2bfloat16(of[mi][nj][2] * inv1);
            p1.y = __float2bfloat16(of[mi][nj][3] * inv1);
            *(__nv_bfloat162*)&g_o[base]             = p0;
            *(__nv_bfloat162*)&g_o[base + 8 * HID]   = p1;
        }
    }
}

// ---------------- LayerNorm over 400 dims (one warp per row) ----------------
__global__ __launch_bounds__(256) void ln_kernel(
    const float* __restrict__ x, const float* __restrict__ gamma,
    const float* __restrict__ beta, float* __restrict__ out)
{
    const int warp = threadIdx.x >> 5, lane = threadIdx.x & 31;
    const size_t row = (size_t)blockIdx.x * 8 + warp;
    const float* xr = x + row * DIN;
    float v[13], s = 0.f, s2 = 0.f;
    #pragma unroll
    for (int i = 0; i < 13; i++) {
        const int idx = lane + 32 * i;
        float val = (idx < DIN) ? xr[idx] : 0.f;
        v[i] = val; s += val; s2 += val * val;
    }
    #pragma unroll
    for (int off = 16; off; off >>= 1) {
        s  += __shfl_xor_sync(0xffffffffu, s,  off);
        s2 += __shfl_xor_sync(0xffffffffu, s2, off);
    }
    const float mu   = s * (1.f / DIN);
    const float var  = s2 * (1.f / DIN) - mu * mu;
    const float rstd = rsqrtf(var + 1e-5f);
    float* orow = out + row * DIN;
    #pragma unroll
    for (int i = 0; i < 13; i++) {
        const int idx = lane + 32 * i;
        if (idx < DIN) orow[idx] = (v[i] - mu) * rstd * gamma[idx] + beta[idx];
    }
}

// ---------------- launch ----------------
extern "C" void kernel_launch(void* const* d_in, const int* in_sizes, int n_in,
                              void* d_out, int out_size)
{
    const float* rgb   = (const float*)d_in[0];
    const float* pose  = (const float*)d_in[1];
    const float* Wq    = (const float*)d_in[2];
    const float* bq    = (const float*)d_in[3];
    const float* Wk    = (const float*)d_in[4];
    const float* bk    = (const float*)d_in[5];
    const float* Wv    = (const float*)d_in[6];
    const float* bv    = (const float*)d_in[7];
    const float* Wp    = (const float*)d_in[8];
    const float* bp    = (const float*)d_in[9];
    const float* gamma = (const float*)d_in[10];
    const float* beta  = (const float*)d_in[11];
    const float* gate  = (const float*)d_in[12];

    void *pq, *pk, *pv, *po, *px;
    cudaGetSymbolAddress(&pq, g_q);
    cudaGetSymbolAddress(&pk, g_k);
    cudaGetSymbolAddress(&pv, g_v);
    cudaGetSymbolAddress(&po, g_o);
    cudaGetSymbolAddress(&px, g_x);

    const int M = NB * SR;          // 65536
    dim3 blk(256);

    // QKV projections
    dim3 gq(HID / 64, M / 128);     // (8, 512)
    gemm_kernel<float, 0><<<gq, blk>>>(rgb,  Wq, bq, nullptr, nullptr, pq, M, HID, DIN);
    gemm_kernel<float, 0><<<gq, blk>>>(pose, Wk, bk, nullptr, nullptr, pk, M, HID, DIN);
    gemm_kernel<float, 0><<<gq, blk>>>(pose, Wv, bv, nullptr, nullptr, pv, M, HID, DIN);

    // attention
    cudaFuncSetAttribute(attn_kernel, cudaFuncAttributeMaxDynamicSharedMemorySize, SMEM_ATTN);
    attn_kernel<<<dim3(SR / 64, NB), blk, SMEM_ATTN>>>();

    // output projection + gated residual
    dim3 gp((DIN + 63) / 64, M / 128);  // (7, 512)
    gemm_kernel<bf16, 1><<<gp, blk>>>((const bf16*)po, Wp, bp, rgb, gate, px, M, DIN, HID);

    // layernorm
    ln_kernel<<<M / 8, blk>>>((const float*)px, gamma, beta, (float*)d_out);
}

// round 2
// speedup vs baseline: 1.5769x; 1.5769x over previous
#include <cuda_runtime.h>
#include <cuda_bf16.h>
#include <math.h>
#include <stdint.h>

using bf16 = __nv_bfloat16;

#define NB   32
#define SR   2048
#define SP   2048
#define DIN  400
#define HID  512

// ---------------- scratch (device globals; no runtime alloc) ----------------
__device__ bf16  g_q[(size_t)NB*SR*HID];
__device__ bf16  g_k[(size_t)NB*SP*HID];
__device__ bf16  g_v[(size_t)NB*SP*HID];
__device__ bf16  g_o[(size_t)NB*SR*HID];
__device__ float g_x[(size_t)NB*SR*DIN];

// ---------------- PTX helpers ----------------
__device__ __forceinline__ void mma16816(float c[4], const uint32_t a[4], const uint32_t b0, const uint32_t b1) {
    asm volatile(
        "mma.sync.aligned.m16n8k16.row.col.f32.bf16.bf16.f32 "
        "{%0,%1,%2,%3}, {%4,%5,%6,%7}, {%8,%9}, {%0,%1,%2,%3};\n"
        : "+f"(c[0]), "+f"(c[1]), "+f"(c[2]), "+f"(c[3])
        : "r"(a[0]), "r"(a[1]), "r"(a[2]), "r"(a[3]), "r"(b0), "r"(b1));
}
__device__ __forceinline__ void ldsm_x4(uint32_t r[4], const void* p) {
    uint32_t addr = (uint32_t)__cvta_generic_to_shared(p);
    asm volatile("ldmatrix.sync.aligned.m8n8.x4.shared.b16 {%0,%1,%2,%3}, [%4];"
                 : "=r"(r[0]), "=r"(r[1]), "=r"(r[2]), "=r"(r[3]) : "r"(addr));
}
__device__ __forceinline__ void ldsm_x4t(uint32_t r[4], const void* p) {
    uint32_t addr = (uint32_t)__cvta_generic_to_shared(p);
    asm volatile("ldmatrix.sync.aligned.m8n8.x4.trans.shared.b16 {%0,%1,%2,%3}, [%4];"
                 : "=r"(r[0]), "=r"(r[1]), "=r"(r[2]), "=r"(r[3]) : "r"(addr));
}
__device__ __forceinline__ void cpa16(void* s, const void* g) {
    uint32_t addr = (uint32_t)__cvta_generic_to_shared(s);
    asm volatile("cp.async.cg.shared.global [%0], [%1], 16;" :: "r"(addr), "l"(g));
}
#define CP_COMMIT() asm volatile("cp.async.commit_group;")
#define CP_WAIT(N)  asm volatile("cp.async.wait_group %0;" :: "n"(N))

// 4-element load+convert helpers (overloaded on source type)
__device__ __forceinline__ void ldcvt4(const float* p, bf16* h) {
    float4 f = *(const float4*)p;
    h[0] = __float2bfloat16(f.x); h[1] = __float2bfloat16(f.y);
    h[2] = __float2bfloat16(f.z); h[3] = __float2bfloat16(f.w);
}
__device__ __forceinline__ void ldcvt4(const bf16* p, bf16* h) {
    *(uint2*)h = *(const uint2*)p;
}

// ---------------- generic GEMM:  C[M,N] = A[M,K] * W[K,N] + bias ----------------
// MODE 0: store bf16 C            MODE 1: store fp32  R + gate*C
template<typename AT, int MODE>
__global__ __launch_bounds__(256) void gemm_kernel(
    const AT* __restrict__ A, const float* __restrict__ W,
    const float* __restrict__ bias, const float* __restrict__ R,
    const float* __restrict__ gatep, void* __restrict__ outp,
    int M, int N, int K)
{
    constexpr int BM = 128, BN = 64, BK = 32, SA = 40, SB = 40;
    __shared__ __align__(16) bf16 As[BM * SA];
    __shared__ __align__(16) bf16 Bs[BN * SB];

    const int tid  = threadIdx.x;
    const int warp = tid >> 5, lane = tid & 31;
    const int wm = warp >> 1, wn = warp & 1;
    const int m0 = blockIdx.y * BM, n0 = blockIdx.x * BN;

    float c[2][4][4];
    #pragma unroll
    for (int i = 0; i < 2; i++)
        #pragma unroll
        for (int j = 0; j < 4; j++)
            #pragma unroll
            for (int t = 0; t < 4; t++) c[i][j][t] = 0.f;

    for (int k0 = 0; k0 < K; k0 += BK) {
        {
            const int kq = tid & 7;
            const int r0 = tid >> 3;
            const int gk = k0 + 4 * kq;
            #pragma unroll
            for (int rr = 0; rr < 4; rr++) {
                const int r = r0 + rr * 32;
                __align__(8) bf16 h[4];
                if (gk < K) ldcvt4(A + (size_t)(m0 + r) * K + gk, h);
                else { h[0]=h[1]=h[2]=h[3]=__float2bfloat16(0.f); }
                *(uint2*)&As[r * SA + 4 * kq] = *(uint2*)h;
            }
        }
        {
            const int cq = tid & 15;
            const int r0 = tid >> 4;
            #pragma unroll
            for (int rr = 0; rr < 2; rr++) {
                const int r  = r0 + rr * 16;
                const int gk = k0 + r;
                const int gn = n0 + 4 * cq;
                float4 f = make_float4(0.f, 0.f, 0.f, 0.f);
                if (gk < K && gn < N) f = *(const float4*)(W + (size_t)gk * N + gn);
                Bs[(4*cq+0) * SB + r] = __float2bfloat16(f.x);
                Bs[(4*cq+1) * SB + r] = __float2bfloat16(f.y);
                Bs[(4*cq+2) * SB + r] = __float2bfloat16(f.z);
                Bs[(4*cq+3) * SB + r] = __float2bfloat16(f.w);
            }
        }
        __syncthreads();
        #pragma unroll
        for (int kk = 0; kk < BK; kk += 16) {
            uint32_t a[2][4];
            #pragma unroll
            for (int mi = 0; mi < 2; mi++) {
                const int mrow = wm * 32 + mi * 16 + (lane >> 2);
                const int kcol = kk + 2 * (lane & 3);
                a[mi][0] = *(const uint32_t*)&As[ mrow      * SA + kcol    ];
                a[mi][1] = *(const uint32_t*)&As[(mrow + 8) * SA + kcol    ];
                a[mi][2] = *(const uint32_t*)&As[ mrow      * SA + kcol + 8];
                a[mi][3] = *(const uint32_t*)&As[(mrow + 8) * SA + kcol + 8];
            }
            #pragma unroll
            for (int nj = 0; nj < 4; nj++) {
                const int nrow = wn * 32 + nj * 8 + (lane >> 2);
                uint32_t b0 = *(const uint32_t*)&Bs[nrow * SB + kk + 2 * (lane & 3)    ];
                uint32_t b1 = *(const uint32_t*)&Bs[nrow * SB + kk + 2 * (lane & 3) + 8];
                #pragma unroll
                for (int mi = 0; mi < 2; mi++) mma16816(c[mi][nj], a[mi], b0, b1);
            }
        }
        __syncthreads();
    }

    float gate = 0.f;
    if (MODE == 1) gate = *gatep;
    #pragma unroll
    for (int mi = 0; mi < 2; mi++) {
        const int r = m0 + wm * 32 + mi * 16 + (lane >> 2);
        #pragma unroll
        for (int nj = 0; nj < 4; nj++) {
            const int cn = n0 + wn * 32 + nj * 8 + 2 * (lane & 3);
            if (cn < N) {
                const float b0 = bias[cn], b1 = bias[cn + 1];
                const float v0 = c[mi][nj][0] + b0, v1 = c[mi][nj][1] + b1;
                const float v2 = c[mi][nj][2] + b0, v3 = c[mi][nj][3] + b1;
                if (MODE == 0) {
                    bf16* out = (bf16*)outp;
                    __nv_bfloat162 p0; p0.x = __float2bfloat16(v0); p0.y = __float2bfloat16(v1);
                    __nv_bfloat162 p1; p1.x = __float2bfloat16(v2); p1.y = __float2bfloat16(v3);
                    *(__nv_bfloat162*)&out[(size_t)r * N + cn]       = p0;
                    *(__nv_bfloat162*)&out[(size_t)(r + 8) * N + cn] = p1;
                } else {
                    float* out = (float*)outp;
                    const size_t i0 = (size_t)r * N + cn;
                    const size_t i1 = (size_t)(r + 8) * N + cn;
                    out[i0]     = R[i0]     + gate * v0;
                    out[i0 + 1] = R[i0 + 1] + gate * v1;
                    out[i1]     = R[i1]     + gate * v2;
                    out[i1 + 1] = R[i1 + 1] + gate * v3;
                }
            }
        }
    }
}

// ---------------- attention v2: cp.async pipeline + ldmatrix ----------------
// smem (bytes):
//   Qs:   0      64 x 520 halves  (66560)
//   Ks:   66560  4 bufs x 64 x 72 halves (36864)
//   Vs:   103424 64 x 520 halves  (66560)   row = key, col = h
//   Ps:   169984 64 x 72 halves   (9216)
//   l:    179200 64 floats        (256)
#define QSTR 520
#define KSTR 72
#define SM_QS 0
#define SM_KS 66560
#define SM_VS 103424
#define SM_PS 169984
#define SM_L  179200
#define SMEM_ATTN 179456

__global__ __launch_bounds__(256, 1) void attn_kernel()
{
    extern __shared__ __align__(16) char sm[];
    bf16*  Qs = (bf16*)(sm + SM_QS);
    bf16*  Ks = (bf16*)(sm + SM_KS);
    bf16*  Vs = (bf16*)(sm + SM_VS);
    bf16*  Ps = (bf16*)(sm + SM_PS);
    float* l  = (float*)(sm + SM_L);

    const int tid = threadIdx.x, warp = tid >> 5, lane = tid & 31;
    const int b = blockIdx.y, q0 = blockIdx.x * 64;
    const bf16* Qg = g_q + ((size_t)b * SR + q0) * HID;
    const bf16* Kg = g_k + (size_t)b * SP * HID;
    const bf16* Vg = g_v + (size_t)b * SP * HID;

    // Q tile 64x512 via cp.async (group 0)
    #pragma unroll
    for (int i = 0; i < 16; i++) {
        const int id = tid + 256 * i;
        const int r = id >> 6, c8 = id & 63;
        cpa16(&Qs[r * QSTR + 8 * c8], Qg + (size_t)r * HID + 8 * c8);
    }
    CP_COMMIT();
    if (tid < 64) l[tid] = 0.f;

    // prologue: K chunks 0..2 (groups 1..3)
    #pragma unroll
    for (int gp = 0; gp < 3; gp++) {
        const bf16* src = Kg + (size_t)((gp >> 3) * 64) * HID + (gp & 7) * 64;
        bf16* dst = Ks + (size_t)(gp & 3) * 64 * KSTR;
        #pragma unroll
        for (int i = 0; i < 2; i++) {
            const int id = tid + 256 * i;
            const int r = id >> 3, c8 = id & 7;
            cpa16(&dst[r * KSTR + 8 * c8], src + (size_t)r * HID + 8 * c8);
        }
        CP_COMMIT();
    }

    const int wmS = warp >> 1, wnS = warp & 1;
    const float scale = 0.044194173824159216f;   // 1/sqrt(512)

    // lane-derived LDSM address components
    const int a_row  = (lane & 15);              // + tile row base
    const int a_col8 = (lane >> 4) * 8;          // + tile col base
    const int b_nrow = (lane & 7) + ((lane >> 4) << 3);
    const int b_koff = (lane & 8);

    float of[4][8][4];
    #pragma unroll
    for (int i = 0; i < 4; i++)
        #pragma unroll
        for (int j = 0; j < 8; j++)
            #pragma unroll
            for (int t = 0; t < 4; t++) of[i][j][t] = 0.f;

    float rs0 = 0.f, rs1 = 0.f;                  // softmax denominators (register accum)

    int g = 0;
    for (int kt = 0; kt < 32; kt++) {
        float sc[4][4];
        #pragma unroll
        for (int j = 0; j < 4; j++)
            #pragma unroll
            for (int t = 0; t < 4; t++) sc[j][t] = 0.f;

        for (int hc = 0; hc < 8; hc++, g++) {
            CP_WAIT(2);           // chunk g landed
            __syncthreads();

            // prefetch K chunk g+3 and V chunk (kt, hc)
            {
                const int gn = g + 3;
                if (gn < 256) {
                    const bf16* src = Kg + (size_t)((gn >> 3) * 64) * HID + (gn & 7) * 64;
                    bf16* dst = Ks + (size_t)(gn & 3) * 64 * KSTR;
                    #pragma unroll
                    for (int i = 0; i < 2; i++) {
                        const int id = tid + 256 * i;
                        const int r = id >> 3, c8 = id & 7;
                        cpa16(&dst[r * KSTR + 8 * c8], src + (size_t)r * HID + 8 * c8);
                    }
                }
                const bf16* vsrc = Vg + (size_t)(kt * 64) * HID + hc * 64;
                #pragma unroll
                for (int i = 0; i < 2; i++) {
                    const int id = tid + 256 * i;
                    const int r = id >> 3, c8 = id & 7;
                    cpa16(&Vs[r * QSTR + hc * 64 + 8 * c8], vsrc + (size_t)r * HID + 8 * c8);
                }
                CP_COMMIT();
            }

            // S mma on chunk g (buffer g&3), k-range = h chunk hc
            const bf16* Kc = Ks + (size_t)(g & 3) * 64 * KSTR;
            #pragma unroll
            for (int kk2 = 0; kk2 < 4; kk2++) {
                uint32_t a[4];
                ldsm_x4(a, &Qs[(wmS * 16 + a_row) * QSTR + hc * 64 + kk2 * 16 + a_col8]);
                #pragma unroll
                for (int ng = 0; ng < 2; ng++) {
                    uint32_t bb[4];
                    ldsm_x4(bb, &Kc[(wnS * 32 + ng * 16 + b_nrow) * KSTR + kk2 * 16 + b_koff]);
                    mma16816(sc[ng * 2 + 0], a, bb[0], bb[1]);
                    mma16816(sc[ng * 2 + 1], a, bb[2], bb[3]);
                }
            }
        }

        // softmax numerator (no max subtraction; logits O(1))
        {
            const int r0 = wmS * 16 + (lane >> 2);
            #pragma unroll
            for (int nj = 0; nj < 4; nj++) {
                const int n = wnS * 32 + nj * 8 + 2 * (lane & 3);
                const float e00 = __expf(sc[nj][0] * scale);
                const float e01 = __expf(sc[nj][1] * scale);
                const float e10 = __expf(sc[nj][2] * scale);
                const float e11 = __expf(sc[nj][3] * scale);
                rs0 += e00 + e01; rs1 += e10 + e11;
                __nv_bfloat162 p0; p0.x = __float2bfloat16(e00); p0.y = __float2bfloat16(e01);
                __nv_bfloat162 p1; p1.x = __float2bfloat16(e10); p1.y = __float2bfloat16(e11);
                *(__nv_bfloat162*)&Ps[ r0      * KSTR + n] = p0;
                *(__nv_bfloat162*)&Ps[(r0 + 8) * KSTR + n] = p1;
            }
        }

        CP_WAIT(0);               // all V chunks landed
        __syncthreads();          // Ps visible + Vs ready

        // O += P V ; warp owns h cols [warp*64, +64)
        #pragma unroll
        for (int kk2 = 0; kk2 < 4; kk2++) {
            uint32_t bb[4][4];
            #pragma unroll
            for (int ng = 0; ng < 4; ng++)
                ldsm_x4t(bb[ng], &Vs[(kk2 * 16 + a_row) * QSTR + warp * 64 + ng * 16 + a_col8]);
            #pragma unroll
            for (int mi = 0; mi < 4; mi++) {
                uint32_t a[4];
                ldsm_x4(a, &Ps[(mi * 16 + a_row) * KSTR + kk2 * 16 + a_col8]);
                #pragma unroll
                for (int ng = 0; ng < 4; ng++) {
                    mma16816(of[mi][ng * 2 + 0], a, bb[ng][0], bb[ng][1]);
                    mma16816(of[mi][ng * 2 + 1], a, bb[ng][2], bb[ng][3]);
                }
            }
        }
        __syncthreads();          // before next kt's V/Ps writes
    }

    // final denominator reduction
    {
        float s0 = rs0, s1 = rs1;
        s0 += __shfl_xor_sync(0xffffffffu, s0, 1);
        s0 += __shfl_xor_sync(0xffffffffu, s0, 2);
        s1 += __shfl_xor_sync(0xffffffffu, s1, 1);
        s1 += __shfl_xor_sync(0xffffffffu, s1, 2);
        if ((lane & 3) == 0) {
            atomicAdd(&l[wmS * 16 + (lane >> 2)],     s0);
            atomicAdd(&l[wmS * 16 + (lane >> 2) + 8], s1);
        }
    }
    __syncthreads();

    // normalize by l and store O (bf16)
    #pragma unroll
    for (int mi = 0; mi < 4; mi++) {
        const int r = mi * 16 + (lane >> 2);
        const float inv0 = 1.f / l[r];
        const float inv1 = 1.f / l[r + 8];
        #pragma unroll
        for (int nj = 0; nj < 8; nj++) {
            const int h = warp * 64 + nj * 8 + 2 * (lane & 3);
            const size_t base = ((size_t)b * SR + q0 + r) * HID + h;
            __nv_bfloat162 p0, p1;
            p0.x = __float2bfloat16(of[mi][nj][0] * inv0);
            p0.y = __float2bfloat16(of[mi][nj][1] * inv0);
            p1.x = __float2bfloat16(of[mi][nj][2] * inv1);
            p1.y = __float2bfloat16(of[mi][nj][3] * inv1);
            *(__nv_bfloat162*)&g_o[base]           = p0;
            *(__nv_bfloat162*)&g_o[base + 8 * HID] = p1;
        }
    }
}

// ---------------- LayerNorm over 400 dims (one warp per row) ----------------
__global__ __launch_bounds__(256) void ln_kernel(
    const float* __restrict__ x, const float* __restrict__ gamma,
    const float* __restrict__ beta, float* __restrict__ out)
{
    const int warp = threadIdx.x >> 5, lane = threadIdx.x & 31;
    const size_t row = (size_t)blockIdx.x * 8 + warp;
    const float* xr = x + row * DIN;
    float v[13], s = 0.f, s2 = 0.f;
    #pragma unroll
    for (int i = 0; i < 13; i++) {
        const int idx = lane + 32 * i;
        float val = (idx < DIN) ? xr[idx] : 0.f;
        v[i] = val; s += val; s2 += val * val;
    }
    #pragma unroll
    for (int off = 16; off; off >>= 1) {
        s  += __shfl_xor_sync(0xffffffffu, s,  off);
        s2 += __shfl_xor_sync(0xffffffffu, s2, off);
    }
    const float mu   = s * (1.f / DIN);
    const float var  = s2 * (1.f / DIN) - mu * mu;
    const float rstd = rsqrtf(var + 1e-5f);
    float* orow = out + row * DIN;
    #pragma unroll
    for (int i = 0; i < 13; i++) {
        const int idx = lane + 32 * i;
        if (idx < DIN) orow[idx] = (v[i] - mu) * rstd * gamma[idx] + beta[idx];
    }
}

// ---------------- launch ----------------
extern "C" void kernel_launch(void* const* d_in, const int* in_sizes, int n_in,
                              void* d_out, int out_size)
{
    const float* rgb   = (const float*)d_in[0];
    const float* pose  = (const float*)d_in[1];
    const float* Wq    = (const float*)d_in[2];
    const float* bq    = (const float*)d_in[3];
    const float* Wk    = (const float*)d_in[4];
    const float* bk    = (const float*)d_in[5];
    const float* Wv    = (const float*)d_in[6];
    const float* bv    = (const float*)d_in[7];
    const float* Wp    = (const float*)d_in[8];
    const float* bp    = (const float*)d_in[9];
    const float* gamma = (const float*)d_in[10];
    const float* beta  = (const float*)d_in[11];
    const float* gate  = (const float*)d_in[12];

    void *pq, *pk, *pv, *po, *px;
    cudaGetSymbolAddress(&pq, g_q);
    cudaGetSymbolAddress(&pk, g_k);
    cudaGetSymbolAddress(&pv, g_v);
    cudaGetSymbolAddress(&po, g_o);
    cudaGetSymbolAddress(&px, g_x);

    const int M = NB * SR;
    dim3 blk(256);

    dim3 gq(HID / 64, M / 128);
    gemm_kernel<float, 0><<<gq, blk>>>(rgb,  Wq, bq, nullptr, nullptr, pq, M, HID, DIN);
    gemm_kernel<float, 0><<<gq, blk>>>(pose, Wk, bk, nullptr, nullptr, pk, M, HID, DIN);
    gemm_kernel<float, 0><<<gq, blk>>>(pose, Wv, bv, nullptr, nullptr, pv, M, HID, DIN);

    cudaFuncSetAttribute(attn_kernel, cudaFuncAttributeMaxDynamicSharedMemorySize, SMEM_ATTN);
    attn_kernel<<<dim3(SR / 64, NB), blk, SMEM_ATTN>>>();

    dim3 gp((DIN + 63) / 64, M / 128);
    gemm_kernel<bf16, 1><<<gp, blk>>>((const bf16*)po, Wp, bp, rgb, gate, px, M, DIN, HID);

    ln_kernel<<<M / 8, blk>>>((const float*)px, gamma, beta, (float*)d_out);
}

// round 3
// speedup vs baseline: 2.0542x; 1.3027x over previous
#include <cuda_runtime.h>
#include <cuda_bf16.h>
#include <math.h>
#include <stdint.h>

using bf16 = __nv_bfloat16;

#define NB   32
#define SR   2048
#define SP   2048
#define DIN  400
#define HID  512
#define KPAD 448            // DIN padded to multiple of 64

// ---------------- scratch (device globals; no runtime alloc) ----------------
__device__ bf16  g_q [(size_t)NB*SR*HID];
__device__ bf16  g_k [(size_t)NB*SP*HID];
__device__ bf16  g_v [(size_t)NB*SP*HID];
__device__ bf16  g_o [(size_t)NB*SR*HID];
__device__ float g_x [(size_t)NB*SR*DIN];
__device__ bf16  g_ar[(size_t)NB*SR*KPAD];      // rgb  bf16, K-padded
__device__ bf16  g_ap[(size_t)NB*SP*KPAD];      // pose bf16, K-padded
__device__ bf16  g_wq[(size_t)HID*KPAD];        // W^T bf16 [n][k]
__device__ bf16  g_wk[(size_t)HID*KPAD];
__device__ bf16  g_wv[(size_t)HID*KPAD];
__device__ bf16  g_wp[(size_t)KPAD*HID];        // Wp^T bf16 [n(448)][k(512)]

// ---------------- PTX helpers ----------------
__device__ __forceinline__ void mma16816(float c[4], const uint32_t a[4], const uint32_t b0, const uint32_t b1) {
    asm volatile(
        "mma.sync.aligned.m16n8k16.row.col.f32.bf16.bf16.f32 "
        "{%0,%1,%2,%3}, {%4,%5,%6,%7}, {%8,%9}, {%0,%1,%2,%3};\n"
        : "+f"(c[0]), "+f"(c[1]), "+f"(c[2]), "+f"(c[3])
        : "r"(a[0]), "r"(a[1]), "r"(a[2]), "r"(a[3]), "r"(b0), "r"(b1));
}
__device__ __forceinline__ void ldsm_x4(uint32_t r[4], const void* p) {
    uint32_t addr = (uint32_t)__cvta_generic_to_shared(p);
    asm volatile("ldmatrix.sync.aligned.m8n8.x4.shared.b16 {%0,%1,%2,%3}, [%4];"
                 : "=r"(r[0]), "=r"(r[1]), "=r"(r[2]), "=r"(r[3]) : "r"(addr));
}
__device__ __forceinline__ void ldsm_x4t(uint32_t r[4], const void* p) {
    uint32_t addr = (uint32_t)__cvta_generic_to_shared(p);
    asm volatile("ldmatrix.sync.aligned.m8n8.x4.trans.shared.b16 {%0,%1,%2,%3}, [%4];"
                 : "=r"(r[0]), "=r"(r[1]), "=r"(r[2]), "=r"(r[3]) : "r"(addr));
}
__device__ __forceinline__ void cpa16(void* s, const void* g) {
    uint32_t addr = (uint32_t)__cvta_generic_to_shared(s);
    asm volatile("cp.async.cg.shared.global [%0], [%1], 16;" :: "r"(addr), "l"(g));
}
#define CP_COMMIT() asm volatile("cp.async.commit_group;")
__device__ __forceinline__ void cp_wait0() { asm volatile("cp.async.wait_group 0;"); }
__device__ __forceinline__ void cp_wait1() { asm volatile("cp.async.wait_group 1;"); }

// ---------------- conversion kernels ----------------
__global__ void cvt_act(const float* __restrict__ in, bf16* __restrict__ out) {
    const int row = blockIdx.x, t = threadIdx.x;   // blockDim = 224
    __nv_bfloat162 h;
    if (t < 200) {
        float2 f = *(const float2*)(in + (size_t)row * DIN + 2 * t);
        h.x = __float2bfloat16(f.x); h.y = __float2bfloat16(f.y);
    } else { h.x = h.y = __float2bfloat16(0.f); }
    *(__nv_bfloat162*)(out + (size_t)row * KPAD + 2 * t) = h;
}
// W[400][512] -> Wt[512][448]
__global__ void cvt_wT(const float* __restrict__ in, bf16* __restrict__ out) {
    const int id = blockIdx.x * 256 + threadIdx.x;          // 512*448
    if (id >= HID * KPAD) return;
    const int col = id % KPAD, row = id / KPAD;
    out[(size_t)row * KPAD + col] = __float2bfloat16(col < DIN ? in[(size_t)col * HID + row] : 0.f);
}
// Wp[512][400] -> Wpt[448][512]
__global__ void cvt_wpT(const float* __restrict__ in, bf16* __restrict__ out) {
    const int id = blockIdx.x * 256 + threadIdx.x;          // 448*512
    if (id >= KPAD * HID) return;
    const int col = id % HID, row = id / HID;
    out[(size_t)row * HID + col] = __float2bfloat16(row < DIN ? in[(size_t)col * DIN + row] : 0.f);
}

// ---------------- pipelined bf16 GEMM:  C[M, 64] = A[M,k] * Bt[n][k]^T ----------------
// NMAT: number of (Bt, bias, out) sets sharing the A tile.  MODE 0: bf16 out. MODE 1: fp32 R + gate*C.
#define G_ASZ 9216      // 128*72 halves per A buffer
#define G_BSZ 4608      // 64*72 halves per B buffer per mat
template<int NMAT, int MODE>
__global__ __launch_bounds__(256) void gemm2_kernel(
    const bf16* __restrict__ A, int ld, int nk,
    const bf16* __restrict__ B0, const bf16* __restrict__ B1,
    const float* __restrict__ bias0, const float* __restrict__ bias1,
    const float* __restrict__ R, const float* __restrict__ gatep,
    void* __restrict__ out0, void* __restrict__ out1, int Nout, int ldout)
{
    extern __shared__ __align__(16) bf16 sm2[];
    bf16* sA = sm2;                       // [2][G_ASZ]
    bf16* sB = sm2 + 2 * G_ASZ;           // [2][NMAT][G_BSZ]

    const int tid  = threadIdx.x;
    const int warp = tid >> 5, lane = tid & 31;
    const int wm = warp >> 1, wn = warp & 1;
    const int m0 = blockIdx.y * 128, n0 = blockIdx.x * 64;

    const int a_row  = lane & 15;
    const int a_col8 = (lane >> 4) * 8;
    const int b_nrow = (lane & 7) + ((lane >> 4) << 3);
    const int b_koff = lane & 8;

    float c[NMAT][2][4][4];
    #pragma unroll
    for (int q = 0; q < NMAT; q++)
        #pragma unroll
        for (int i = 0; i < 2; i++)
            #pragma unroll
            for (int j = 0; j < 4; j++)
                #pragma unroll
                for (int t = 0; t < 4; t++) c[q][i][j][t] = 0.f;

    auto load_stage = [&](int ks, int buf) {
        const bf16* Asrc = A + (size_t)m0 * ld + ks * 64;
        #pragma unroll
        for (int i = 0; i < 4; i++) {
            const int id = tid + 256 * i;
            const int r = id >> 3, c8 = id & 7;
            cpa16(&sA[buf * G_ASZ + r * 72 + 8 * c8], Asrc + (size_t)r * ld + 8 * c8);
        }
        #pragma unroll
        for (int mat = 0; mat < NMAT; mat++) {
            const bf16* Bsrc = (mat ? B1 : B0) + (size_t)n0 * ld + ks * 64;
            #pragma unroll
            for (int i = 0; i < 2; i++) {
                const int id = tid + 256 * i;
                const int r = id >> 3, c8 = id & 7;
                cpa16(&sB[(buf * NMAT + mat) * G_BSZ + r * 72 + 8 * c8], Bsrc + (size_t)r * ld + 8 * c8);
            }
        }
        CP_COMMIT();
    };

    load_stage(0, 0);
    for (int t = 0; t < nk; t++) {
        cp_wait0();
        __syncthreads();
        if (t + 1 < nk) load_stage(t + 1, (t + 1) & 1);
        const int buf = t & 1;
        const bf16* As_ = sA + buf * G_ASZ;
        #pragma unroll
        for (int kk = 0; kk < 4; kk++) {
            uint32_t a[2][4];
            #pragma unroll
            for (int mi = 0; mi < 2; mi++)
                ldsm_x4(a[mi], &As_[(wm * 32 + mi * 16 + a_row) * 72 + kk * 16 + a_col8]);
            #pragma unroll
            for (int mat = 0; mat < NMAT; mat++) {
                const bf16* Bs_ = sB + (buf * NMAT + mat) * G_BSZ;
                #pragma unroll
                for (int ng = 0; ng < 2; ng++) {
                    uint32_t bb[4];
                    ldsm_x4(bb, &Bs_[(wn * 32 + ng * 16 + b_nrow) * 72 + kk * 16 + b_koff]);
                    #pragma unroll
                    for (int mi = 0; mi < 2; mi++) {
                        mma16816(c[mat][mi][ng * 2 + 0], a[mi], bb[0], bb[1]);
                        mma16816(c[mat][mi][ng * 2 + 1], a[mi], bb[2], bb[3]);
                    }
                }
            }
        }
        __syncthreads();
    }

    float gate = 0.f;
    if (MODE == 1) gate = *gatep;
    #pragma unroll
    for (int mat = 0; mat < NMAT; mat++) {
        const float* bias = mat ? bias1 : bias0;
        #pragma unroll
        for (int mi = 0; mi < 2; mi++) {
            const int r = m0 + wm * 32 + mi * 16 + (lane >> 2);
            #pragma unroll
            for (int nj = 0; nj < 4; nj++) {
                const int cn = n0 + wn * 32 + nj * 8 + 2 * (lane & 3);
                if (cn < Nout) {
                    const float b0 = bias[cn], b1 = bias[cn + 1];
                    const float v0 = c[mat][mi][nj][0] + b0, v1 = c[mat][mi][nj][1] + b1;
                    const float v2 = c[mat][mi][nj][2] + b0, v3 = c[mat][mi][nj][3] + b1;
                    if (MODE == 0) {
                        bf16* out = (bf16*)(mat ? out1 : out0);
                        __nv_bfloat162 p0; p0.x = __float2bfloat16(v0); p0.y = __float2bfloat16(v1);
                        __nv_bfloat162 p1; p1.x = __float2bfloat16(v2); p1.y = __float2bfloat16(v3);
                        *(__nv_bfloat162*)&out[(size_t)r * ldout + cn]       = p0;
                        *(__nv_bfloat162*)&out[(size_t)(r + 8) * ldout + cn] = p1;
                    } else {
                        float* out = (float*)out0;
                        const size_t i0 = (size_t)r * ldout + cn;
                        const size_t i1 = (size_t)(r + 8) * ldout + cn;
                        out[i0]     = R[i0]     + gate * v0;
                        out[i0 + 1] = R[i0 + 1] + gate * v1;
                        out[i1]     = R[i1]     + gate * v2;
                        out[i1 + 1] = R[i1 + 1] + gate * v3;
                    }
                }
            }
        }
    }
}

// ---------------- attention v3: full-tile K/V single buffers, interleaved cp.async ----------------
// smem halves: Qs[64][520] | Ks[64][520] | Vs[64][520] | Ps[64][72] | l[64]f32
#define QSTR 520
#define PSTR 72
#define A_QS 0
#define A_KS 33280
#define A_VS 66560
#define A_PS 99840
#define A_L_BYTES 208896
#define SMEM_ATTN 209152

__global__ __launch_bounds__(256, 1) void attn_kernel()
{
    extern __shared__ __align__(16) char sm[];
    bf16*  Qs = (bf16*)sm + A_QS;
    bf16*  Ks = (bf16*)sm + A_KS;
    bf16*  Vs = (bf16*)sm + A_VS;
    bf16*  Ps = (bf16*)sm + A_PS;
    float* l  = (float*)(sm + A_L_BYTES);

    const int tid = threadIdx.x, warp = tid >> 5, lane = tid & 31;
    const int b = blockIdx.y, q0 = blockIdx.x * 64;
    const bf16* Qg = g_q + ((size_t)b * SR + q0) * HID;
    const bf16* Kg = g_k + (size_t)b * SP * HID;
    const bf16* Vg = g_v + (size_t)b * SP * HID;

    auto load64x512 = [&](bf16* dst, const bf16* src) {
        #pragma unroll
        for (int i = 0; i < 16; i++) {
            const int id = tid + 256 * i;
            const int r = id >> 6, c8 = id & 63;
            cpa16(&dst[r * QSTR + 8 * c8], src + (size_t)r * HID + 8 * c8);
        }
        CP_COMMIT();
    };

    load64x512(Qs, Qg);            // group: Q
    load64x512(Ks, Kg);            // group: K0
    load64x512(Vs, Vg);            // group: V0
    if (tid < 64) l[tid] = 0.f;

    const int wmS = warp >> 1, wnS = warp & 1;
    const float scale = 0.044194173824159216f;   // 1/sqrt(512)

    const int a_row  = lane & 15;
    const int a_col8 = (lane >> 4) * 8;
    const int b_nrow = (lane & 7) + ((lane >> 4) << 3);
    const int b_koff = lane & 8;

    float of[4][8][4];
    #pragma unroll
    for (int i = 0; i < 4; i++)
        #pragma unroll
        for (int j = 0; j < 8; j++)
            #pragma unroll
            for (int t = 0; t < 4; t++) of[i][j][t] = 0.f;

    float rs0 = 0.f, rs1 = 0.f;

    for (int kt = 0; kt < 32; kt++) {
        // ---- wait K(kt) (leaves newest group pending) ----
        if (kt < 31) cp_wait1(); else cp_wait0();
        __syncthreads();

        // ---- S = Q K^T over full 512 h ----
        float sc[4][4];
        #pragma unroll
        for (int j = 0; j < 4; j++)
            #pragma unroll
            for (int t = 0; t < 4; t++) sc[j][t] = 0.f;

        #pragma unroll 8
        for (int ks = 0; ks < 32; ks++) {
            uint32_t a[4];
            ldsm_x4(a, &Qs[(wmS * 16 + a_row) * QSTR + ks * 16 + a_col8]);
            #pragma unroll
            for (int ng = 0; ng < 2; ng++) {
                uint32_t bb[4];
                ldsm_x4(bb, &Ks[(wnS * 32 + ng * 16 + b_nrow) * QSTR + ks * 16 + b_koff]);
                mma16816(sc[ng * 2 + 0], a, bb[0], bb[1]);
                mma16816(sc[ng * 2 + 1], a, bb[2], bb[3]);
            }
        }
        __syncthreads();                       // all warps done reading Ks

        if (kt < 31) load64x512(Ks, Kg + (size_t)(kt + 1) * 64 * HID);

        // ---- softmax numerator (no max subtraction; logits O(1)) ----
        {
            const int r0 = wmS * 16 + (lane >> 2);
            #pragma unroll
            for (int nj = 0; nj < 4; nj++) {
                const int n = wnS * 32 + nj * 8 + 2 * (lane & 3);
                const float e00 = __expf(sc[nj][0] * scale);
                const float e01 = __expf(sc[nj][1] * scale);
                const float e10 = __expf(sc[nj][2] * scale);
                const float e11 = __expf(sc[nj][3] * scale);
                rs0 += e00 + e01; rs1 += e10 + e11;
                __nv_bfloat162 p0; p0.x = __float2bfloat16(e00); p0.y = __float2bfloat16(e01);
                __nv_bfloat162 p1; p1.x = __float2bfloat16(e10); p1.y = __float2bfloat16(e11);
                *(__nv_bfloat162*)&Ps[ r0      * PSTR + n] = p0;
                *(__nv_bfloat162*)&Ps[(r0 + 8) * PSTR + n] = p1;
            }
        }

        // ---- wait V(kt); Ps visible ----
        if (kt < 31) cp_wait1(); else cp_wait0();
        __syncthreads();

        // ---- O += P V ; warp owns h cols [warp*64, +64) ----
        #pragma unroll
        for (int kk2 = 0; kk2 < 4; kk2++) {
            uint32_t bb[4][4];
            #pragma unroll
            for (int ng = 0; ng < 4; ng++)
                ldsm_x4t(bb[ng], &Vs[(kk2 * 16 + a_row) * QSTR + warp * 64 + ng * 16 + a_col8]);
            #pragma unroll
            for (int mi = 0; mi < 4; mi++) {
                uint32_t a[4];
                ldsm_x4(a, &Ps[(mi * 16 + a_row) * PSTR + kk2 * 16 + a_col8]);
                #pragma unroll
                for (int ng = 0; ng < 4; ng++) {
                    mma16816(of[mi][ng * 2 + 0], a, bb[ng][0], bb[ng][1]);
                    mma16816(of[mi][ng * 2 + 1], a, bb[ng][2], bb[ng][3]);
                }
            }
        }
        __syncthreads();                       // all warps done reading Vs/Ps

        if (kt < 31) load64x512(Vs, Vg + (size_t)(kt + 1) * 64 * HID);
    }

    // ---- denominators ----
    {
        float s0 = rs0, s1 = rs1;
        s0 += __shfl_xor_sync(0xffffffffu, s0, 1);
        s0 += __shfl_xor_sync(0xffffffffu, s0, 2);
        s1 += __shfl_xor_sync(0xffffffffu, s1, 1);
        s1 += __shfl_xor_sync(0xffffffffu, s1, 2);
        if ((lane & 3) == 0) {
            atomicAdd(&l[wmS * 16 + (lane >> 2)],     s0);
            atomicAdd(&l[wmS * 16 + (lane >> 2) + 8], s1);
        }
    }
    __syncthreads();

    #pragma unroll
    for (int mi = 0; mi < 4; mi++) {
        const int r = mi * 16 + (lane >> 2);
        const float inv0 = 1.f / l[r];
        const float inv1 = 1.f / l[r + 8];
        #pragma unroll
        for (int nj = 0; nj < 8; nj++) {
            const int h = warp * 64 + nj * 8 + 2 * (lane & 3);
            const size_t base = ((size_t)b * SR + q0 + r) * HID + h;
            __nv_bfloat162 p0, p1;
            p0.x = __float2bfloat16(of[mi][nj][0] * inv0);
            p0.y = __float2bfloat16(of[mi][nj][1] * inv0);
            p1.x = __float2bfloat16(of[mi][nj][2] * inv1);
            p1.y = __float2bfloat16(of[mi][nj][3] * inv1);
            *(__nv_bfloat162*)&g_o[base]           = p0;
            *(__nv_bfloat162*)&g_o[base + 8 * HID] = p1;
        }
    }
}

// ---------------- LayerNorm over 400 dims (one warp per row) ----------------
__global__ __launch_bounds__(256) void ln_kernel(
    const float* __restrict__ x, const float* __restrict__ gamma,
    const float* __restrict__ beta, float* __restrict__ out)
{
    const int warp = threadIdx.x >> 5, lane = threadIdx.x & 31;
    const size_t row = (size_t)blockIdx.x * 8 + warp;
    const float* xr = x + row * DIN;
    float v[13], s = 0.f, s2 = 0.f;
    #pragma unroll
    for (int i = 0; i < 13; i++) {
        const int idx = lane + 32 * i;
        float val = (idx < DIN) ? xr[idx] : 0.f;
        v[i] = val; s += val; s2 += val * val;
    }
    #pragma unroll
    for (int off = 16; off; off >>= 1) {
        s  += __shfl_xor_sync(0xffffffffu, s,  off);
        s2 += __shfl_xor_sync(0xffffffffu, s2, off);
    }
    const float mu   = s * (1.f / DIN);
    const float var  = s2 * (1.f / DIN) - mu * mu;
    const float rstd = rsqrtf(var + 1e-5f);
    float* orow = out + row * DIN;
    #pragma unroll
    for (int i = 0; i < 13; i++) {
        const int idx = lane + 32 * i;
        if (idx < DIN) orow[idx] = (v[i] - mu) * rstd * gamma[idx] + beta[idx];
    }
}

// ---------------- launch ----------------
extern "C" void kernel_launch(void* const* d_in, const int* in_sizes, int n_in,
                              void* d_out, int out_size)
{
    const float* rgb   = (const float*)d_in[0];
    const float* pose  = (const float*)d_in[1];
    const float* Wq    = (const float*)d_in[2];
    const float* bq    = (const float*)d_in[3];
    const float* Wk    = (const float*)d_in[4];
    const float* bk    = (const float*)d_in[5];
    const float* Wv    = (const float*)d_in[6];
    const float* bv    = (const float*)d_in[7];
    const float* Wp    = (const float*)d_in[8];
    const float* bp    = (const float*)d_in[9];
    const float* gamma = (const float*)d_in[10];
    const float* beta  = (const float*)d_in[11];
    const float* gate  = (const float*)d_in[12];

    void *pq, *pk, *pv, *po, *px, *par, *pap, *pwq, *pwk, *pwv, *pwp;
    cudaGetSymbolAddress(&pq,  g_q);
    cudaGetSymbolAddress(&pk,  g_k);
    cudaGetSymbolAddress(&pv,  g_v);
    cudaGetSymbolAddress(&po,  g_o);
    cudaGetSymbolAddress(&px,  g_x);
    cudaGetSymbolAddress(&par, g_ar);
    cudaGetSymbolAddress(&pap, g_ap);
    cudaGetSymbolAddress(&pwq, g_wq);
    cudaGetSymbolAddress(&pwk, g_wk);
    cudaGetSymbolAddress(&pwv, g_wv);
    cudaGetSymbolAddress(&pwp, g_wp);

    const int M = NB * SR;    // 65536

    // --- conversions ---
    cvt_act<<<M, 224>>>(rgb,  (bf16*)par);
    cvt_act<<<M, 224>>>(pose, (bf16*)pap);
    cvt_wT <<<(HID*KPAD + 255)/256, 256>>>(Wq, (bf16*)pwq);
    cvt_wT <<<(HID*KPAD + 255)/256, 256>>>(Wk, (bf16*)pwk);
    cvt_wT <<<(HID*KPAD + 255)/256, 256>>>(Wv, (bf16*)pwv);
    cvt_wpT<<<(KPAD*HID + 255)/256, 256>>>(Wp, (bf16*)pwp);

    // --- GEMMs ---
    const int smem1 = (2*G_ASZ + 2*1*G_BSZ) * 2;   // 55296 B
    const int smem2 = (2*G_ASZ + 2*2*G_BSZ) * 2;   // 73728 B
    cudaFuncSetAttribute(gemm2_kernel<1,0>, cudaFuncAttributeMaxDynamicSharedMemorySize, smem1);
    cudaFuncSetAttribute(gemm2_kernel<2,0>, cudaFuncAttributeMaxDynamicSharedMemorySize, smem2);
    cudaFuncSetAttribute(gemm2_kernel<1,1>, cudaFuncAttributeMaxDynamicSharedMemorySize, smem1);

    dim3 blk(256);
    dim3 gq(HID / 64, M / 128);
    gemm2_kernel<1,0><<<gq, blk, smem1>>>((const bf16*)par, KPAD, KPAD/64,
        (const bf16*)pwq, nullptr, bq, nullptr, nullptr, nullptr, pq, nullptr, HID, HID);
    gemm2_kernel<2,0><<<gq, blk, smem2>>>((const bf16*)pap, KPAD, KPAD/64,
        (const bf16*)pwk, (const bf16*)pwv, bk, bv, nullptr, nullptr, pk, pv, HID, HID);

    // --- attention ---
    cudaFuncSetAttribute(attn_kernel, cudaFuncAttributeMaxDynamicSharedMemorySize, SMEM_ATTN);
    attn_kernel<<<dim3(SR / 64, NB), blk, SMEM_ATTN>>>();

    // --- projection + gated residual ---
    dim3 gp(KPAD / 64, M / 128);    // 7 n-blocks cover 448 (stores predicated to 400)
    gemm2_kernel<1,1><<<gp, blk, smem1>>>((const bf16*)po, HID, HID/64,
        (const bf16*)pwp, nullptr, bp, nullptr, rgb, gate, px, nullptr, DIN, DIN);

    // --- layernorm ---
    ln_kernel<<<M / 8, blk>>>((const float*)px, gamma, beta, (float*)d_out);
}

// round 6
// speedup vs baseline: 3.0732x; 1.4960x over previous
#include <cuda_runtime.h>
#include <cuda_bf16.h>
#include <math.h>
#include <stdint.h>

using bf16 = __nv_bfloat16;

#define NB   32
#define SR   2048
#define SP   2048
#define DIN  400
#define HID  512
#define KPAD 448            // DIN padded to multiple of 64

// ---------------- scratch (device globals; no runtime alloc) ----------------
__device__ bf16  g_q [(size_t)NB*SR*HID];
__device__ bf16  g_k [(size_t)NB*SP*HID];
__device__ bf16  g_v [(size_t)NB*SP*HID];
__device__ bf16  g_o [(size_t)NB*SR*HID];
__device__ float g_x [(size_t)NB*SR*DIN];
__device__ bf16  g_ar[(size_t)NB*SR*KPAD];      // rgb  bf16, K-padded
__device__ bf16  g_ap[(size_t)NB*SP*KPAD];      // pose bf16, K-padded
__device__ bf16  g_wq[(size_t)HID*KPAD];        // W^T bf16 [n][k]
__device__ bf16  g_wk[(size_t)HID*KPAD];
__device__ bf16  g_wv[(size_t)HID*KPAD];
__device__ bf16  g_wp[(size_t)KPAD*HID];        // Wp^T bf16 [n(448)][k(512)]

// ---------------- PTX helpers ----------------
__device__ __forceinline__ void mma16816(float c[4], const uint32_t a[4], const uint32_t b0, const uint32_t b1) {
    asm volatile(
        "mma.sync.aligned.m16n8k16.row.col.f32.bf16.bf16.f32 "
        "{%0,%1,%2,%3}, {%4,%5,%6,%7}, {%8,%9}, {%0,%1,%2,%3};\n"
        : "+f"(c[0]), "+f"(c[1]), "+f"(c[2]), "+f"(c[3])
        : "r"(a[0]), "r"(a[1]), "r"(a[2]), "r"(a[3]), "r"(b0), "r"(b1));
}
__device__ __forceinline__ void ldsm_x4(uint32_t r[4], const void* p) {
    uint32_t addr = (uint32_t)__cvta_generic_to_shared(p);
    asm volatile("ldmatrix.sync.aligned.m8n8.x4.shared.b16 {%0,%1,%2,%3}, [%4];"
                 : "=r"(r[0]), "=r"(r[1]), "=r"(r[2]), "=r"(r[3]) : "r"(addr));
}
__device__ __forceinline__ void ldsm_x4t(uint32_t r[4], const void* p) {
    uint32_t addr = (uint32_t)__cvta_generic_to_shared(p);
    asm volatile("ldmatrix.sync.aligned.m8n8.x4.trans.shared.b16 {%0,%1,%2,%3}, [%4];"
                 : "=r"(r[0]), "=r"(r[1]), "=r"(r[2]), "=r"(r[3]) : "r"(addr));
}
__device__ __forceinline__ void cpa16(void* s, const void* g) {
    uint32_t addr = (uint32_t)__cvta_generic_to_shared(s);
    asm volatile("cp.async.cg.shared.global [%0], [%1], 16;" :: "r"(addr), "l"(g));
}
#define CP_COMMIT() asm volatile("cp.async.commit_group;")
__device__ __forceinline__ void cp_wait0() { asm volatile("cp.async.wait_group 0;"); }
__device__ __forceinline__ void cp_wait1() { asm volatile("cp.async.wait_group 1;"); }

// ---------------- conversion kernels ----------------
// activations: [rows][400] f32 -> [rows][448] bf16 (zero padded). one uint4 (8 halves) per thread-iter
__global__ __launch_bounds__(256) void cvt_act(const float* __restrict__ in, bf16* __restrict__ out, int rows) {
    const int total = rows * (KPAD / 8);
    for (int id = blockIdx.x * 256 + threadIdx.x; id < total; id += gridDim.x * 256) {
        const int row = id / (KPAD / 8), c8 = id % (KPAD / 8);
        __align__(16) bf16 h[8];
        if (c8 < DIN / 8) {
            float4 f0 = *(const float4*)(in + (size_t)row * DIN + 8 * c8);
            float4 f1 = *(const float4*)(in + (size_t)row * DIN + 8 * c8 + 4);
            h[0] = __float2bfloat16(f0.x); h[1] = __float2bfloat16(f0.y);
            h[2] = __float2bfloat16(f0.z); h[3] = __float2bfloat16(f0.w);
            h[4] = __float2bfloat16(f1.x); h[5] = __float2bfloat16(f1.y);
            h[6] = __float2bfloat16(f1.z); h[7] = __float2bfloat16(f1.w);
        } else {
            #pragma unroll
            for (int i = 0; i < 8; i++) h[i] = __float2bfloat16(0.f);
        }
        *(uint4*)(out + (size_t)row * KPAD + 8 * c8) = *(const uint4*)h;
    }
}
// fused weight transpose+convert: blockIdx.y selects matrix.
//  y<3: W[400][512] -> Wt[512][448]   (q,k,v)
//  y=3: Wp[512][400] -> Wpt[448][512]
__global__ __launch_bounds__(256) void cvt_w_all(
    const float* __restrict__ Wq, const float* __restrict__ Wk,
    const float* __restrict__ Wv, const float* __restrict__ Wp,
    bf16* __restrict__ oq, bf16* __restrict__ ok,
    bf16* __restrict__ ov, bf16* __restrict__ op)
{
    const int id = blockIdx.x * 256 + threadIdx.x;
    const int mat = blockIdx.y;
    if (mat < 3) {
        if (id >= HID * KPAD) return;
        const float* in = mat == 0 ? Wq : (mat == 1 ? Wk : Wv);
        bf16* out = mat == 0 ? oq : (mat == 1 ? ok : ov);
        const int col = id % KPAD, row = id / KPAD;
        out[(size_t)row * KPAD + col] = __float2bfloat16(col < DIN ? in[(size_t)col * HID + row] : 0.f);
    } else {
        if (id >= KPAD * HID) return;
        const int col = id % HID, row = id / HID;
        op[(size_t)row * HID + col] = __float2bfloat16(row < DIN ? Wp[(size_t)col * DIN + row] : 0.f);
    }
}

// ---------------- pipelined bf16 GEMM v3: 3-stage, occ-2 ----------------
// C[M,64-tile] = A[M][k] * Bt[n][k]^T  (+bias). MODE 0: bf16 out. MODE 1: fp32 R + gate*C.
#define G_ASZ 9216      // 128*72 halves
#define G_BSZ 4608      // 64*72 halves
#define G_STG 13824     // per-stage halves
template<int MODE>
__global__ __launch_bounds__(256, 2) void gemm3_kernel(
    const bf16* __restrict__ A, int ld, int nk,
    const bf16* __restrict__ B, const float* __restrict__ bias,
    const float* __restrict__ R, const float* __restrict__ gatep,
    void* __restrict__ outp, int Nout, int ldout)
{
    extern __shared__ __align__(16) bf16 sm2[];   // [3][G_STG]

    const int tid  = threadIdx.x;
    const int warp = tid >> 5, lane = tid & 31;
    const int wm = warp >> 1, wn = warp & 1;
    const int m0 = blockIdx.y * 128, n0 = blockIdx.x * 64;

    const int a_row  = lane & 15;
    const int a_col8 = (lane >> 4) * 8;
    const int b_nrow = (lane & 7) + ((lane >> 4) << 3);
    const int b_koff = lane & 8;

    float c[2][4][4];
    #pragma unroll
    for (int i = 0; i < 2; i++)
        #pragma unroll
        for (int j = 0; j < 4; j++)
            #pragma unroll
            for (int t = 0; t < 4; t++) c[i][j][t] = 0.f;

    auto load_stage = [&](int ks, int buf) {
        bf16* sA = sm2 + buf * G_STG;
        bf16* sB = sA + G_ASZ;
        const bf16* Asrc = A + (size_t)m0 * ld + ks * 64;
        #pragma unroll
        for (int i = 0; i < 4; i++) {
            const int id = tid + 256 * i;
            const int r = id >> 3, c8 = id & 7;
            cpa16(&sA[r * 72 + 8 * c8], Asrc + (size_t)r * ld + 8 * c8);
        }
        const bf16* Bsrc = B + (size_t)n0 * ld + ks * 64;
        #pragma unroll
        for (int i = 0; i < 2; i++) {
            const int id = tid + 256 * i;
            const int r = id >> 3, c8 = id & 7;
            cpa16(&sB[r * 72 + 8 * c8], Bsrc + (size_t)r * ld + 8 * c8);
        }
        CP_COMMIT();
    };

    load_stage(0, 0);
    if (nk > 1) load_stage(1, 1);
    int buf = 0;
    for (int t = 0; t < nk; t++) {
        if (t + 1 < nk) cp_wait1(); else cp_wait0();
        __syncthreads();
        if (t + 2 < nk) load_stage(t + 2, (buf + 2) % 3);

        const bf16* As_ = sm2 + buf * G_STG;
        const bf16* Bs_ = As_ + G_ASZ;
        #pragma unroll
        for (int kk = 0; kk < 4; kk++) {
            uint32_t a[2][4];
            #pragma unroll
            for (int mi = 0; mi < 2; mi++)
                ldsm_x4(a[mi], &As_[(wm * 32 + mi * 16 + a_row) * 72 + kk * 16 + a_col8]);
            #pragma unroll
            for (int ng = 0; ng < 2; ng++) {
                uint32_t bb[4];
                ldsm_x4(bb, &Bs_[(wn * 32 + ng * 16 + b_nrow) * 72 + kk * 16 + b_koff]);
                #pragma unroll
                for (int mi = 0; mi < 2; mi++) {
                    mma16816(c[mi][ng * 2 + 0], a[mi], bb[0], bb[1]);
                    mma16816(c[mi][ng * 2 + 1], a[mi], bb[2], bb[3]);
                }
            }
        }
        __syncthreads();
        buf = (buf + 1) % 3;
    }

    float gate = 0.f;
    if (MODE == 1) gate = *gatep;
    #pragma unroll
    for (int mi = 0; mi < 2; mi++) {
        const int r = m0 + wm * 32 + mi * 16 + (lane >> 2);
        #pragma unroll
        for (int nj = 0; nj < 4; nj++) {
            const int cn = n0 + wn * 32 + nj * 8 + 2 * (lane & 3);
            if (cn < Nout) {
                const float b0 = bias[cn], b1 = bias[cn + 1];
                const float v0 = c[mi][nj][0] + b0, v1 = c[mi][nj][1] + b1;
                const float v2 = c[mi][nj][2] + b0, v3 = c[mi][nj][3] + b1;
                if (MODE == 0) {
                    bf16* out = (bf16*)outp;
                    __nv_bfloat162 p0; p0.x = __float2bfloat16(v0); p0.y = __float2bfloat16(v1);
                    __nv_bfloat162 p1; p1.x = __float2bfloat16(v2); p1.y = __float2bfloat16(v3);
                    *(__nv_bfloat162*)&out[(size_t)r * ldout + cn]       = p0;
                    *(__nv_bfloat162*)&out[(size_t)(r + 8) * ldout + cn] = p1;
                } else {
                    float* out = (float*)outp;
                    const size_t i0 = (size_t)r * ldout + cn;
                    const size_t i1 = (size_t)(r + 8) * ldout + cn;
                    out[i0]     = R[i0]     + gate * v0;
                    out[i0 + 1] = R[i0 + 1] + gate * v1;
                    out[i1]     = R[i1]     + gate * v2;
                    out[i1 + 1] = R[i1 + 1] + gate * v3;
                }
            }
        }
    }
}

// ---------------- attention v3: full-tile K/V single buffers, interleaved cp.async ----------------
#define QSTR 520
#define PSTR 72
#define A_QS 0
#define A_KS 33280
#define A_VS 66560
#define A_PS 99840
#define A_L_BYTES 208896
#define SMEM_ATTN 209152

__global__ __launch_bounds__(256, 1) void attn_kernel()
{
    extern __shared__ __align__(16) char sm[];
    bf16*  Qs = (bf16*)sm + A_QS;
    bf16*  Ks = (bf16*)sm + A_KS;
    bf16*  Vs = (bf16*)sm + A_VS;
    bf16*  Ps = (bf16*)sm + A_PS;
    float* l  = (float*)(sm + A_L_BYTES);

    const int tid = threadIdx.x, warp = tid >> 5, lane = tid & 31;
    const int b = blockIdx.y, q0 = blockIdx.x * 64;
    const bf16* Qg = g_q + ((size_t)b * SR + q0) * HID;
    const bf16* Kg = g_k + (size_t)b * SP * HID;
    const bf16* Vg = g_v + (size_t)b * SP * HID;

    auto load64x512 = [&](bf16* dst, const bf16* src) {
        #pragma unroll
        for (int i = 0; i < 16; i++) {
            const int id = tid + 256 * i;
            const int r = id >> 6, c8 = id & 63;
            cpa16(&dst[r * QSTR + 8 * c8], src + (size_t)r * HID + 8 * c8);
        }
        CP_COMMIT();
    };

    load64x512(Qs, Qg);
    load64x512(Ks, Kg);
    load64x512(Vs, Vg);
    if (tid < 64) l[tid] = 0.f;

    const int wmS = warp >> 1, wnS = warp & 1;
    const float scale = 0.044194173824159216f;

    const int a_row  = lane & 15;
    const int a_col8 = (lane >> 4) * 8;
    const int b_nrow = (lane & 7) + ((lane >> 4) << 3);
    const int b_koff = lane & 8;

    float of[4][8][4];
    #pragma unroll
    for (int i = 0; i < 4; i++)
        #pragma unroll
        for (int j = 0; j < 8; j++)
            #pragma unroll
            for (int t = 0; t < 4; t++) of[i][j][t] = 0.f;

    float rs0 = 0.f, rs1 = 0.f;

    for (int kt = 0; kt < 32; kt++) {
        if (kt < 31) cp_wait1(); else cp_wait0();
        __syncthreads();

        float sc[4][4];
        #pragma unroll
        for (int j = 0; j < 4; j++)
            #pragma unroll
            for (int t = 0; t < 4; t++) sc[j][t] = 0.f;

        #pragma unroll 8
        for (int ks = 0; ks < 32; ks++) {
            uint32_t a[4];
            ldsm_x4(a, &Qs[(wmS * 16 + a_row) * QSTR + ks * 16 + a_col8]);
            #pragma unroll
            for (int ng = 0; ng < 2; ng++) {
                uint32_t bb[4];
                ldsm_x4(bb, &Ks[(wnS * 32 + ng * 16 + b_nrow) * QSTR + ks * 16 + b_koff]);
                mma16816(sc[ng * 2 + 0], a, bb[0], bb[1]);
                mma16816(sc[ng * 2 + 1], a, bb[2], bb[3]);
            }
        }
        __syncthreads();

        if (kt < 31) load64x512(Ks, Kg + (size_t)(kt + 1) * 64 * HID);

        {
            const int r0 = wmS * 16 + (lane >> 2);
            #pragma unroll
            for (int nj = 0; nj < 4; nj++) {
                const int n = wnS * 32 + nj * 8 + 2 * (lane & 3);
                const float e00 = __expf(sc[nj][0] * scale);
                const float e01 = __expf(sc[nj][1] * scale);
                const float e10 = __expf(sc[nj][2] * scale);
                const float e11 = __expf(sc[nj][3] * scale);
                rs0 += e00 + e01; rs1 += e10 + e11;
                __nv_bfloat162 p0; p0.x = __float2bfloat16(e00); p0.y = __float2bfloat16(e01);
                __nv_bfloat162 p1; p1.x = __float2bfloat16(e10); p1.y = __float2bfloat16(e11);
                *(__nv_bfloat162*)&Ps[ r0      * PSTR + n] = p0;
                *(__nv_bfloat162*)&Ps[(r0 + 8) * PSTR + n] = p1;
            }
        }

        if (kt < 31) cp_wait1(); else cp_wait0();
        __syncthreads();

        #pragma unroll
        for (int kk2 = 0; kk2 < 4; kk2++) {
            uint32_t bb[4][4];
            #pragma unroll
            for (int ng = 0; ng < 4; ng++)
                ldsm_x4t(bb[ng], &Vs[(kk2 * 16 + a_row) * QSTR + warp * 64 + ng * 16 + a_col8]);
            #pragma unroll
            for (int mi = 0; mi < 4; mi++) {
                uint32_t a[4];
                ldsm_x4(a, &Ps[(mi * 16 + a_row) * PSTR + kk2 * 16 + a_col8]);
                #pragma unroll
                for (int ng = 0; ng < 4; ng++) {
                    mma16816(of[mi][ng * 2 + 0], a, bb[ng][0], bb[ng][1]);
                    mma16816(of[mi][ng * 2 + 1], a, bb[ng][2], bb[ng][3]);
                }
            }
        }
        __syncthreads();

        if (kt < 31) load64x512(Vs, Vg + (size_t)(kt + 1) * 64 * HID);
    }

    {
        float s0 = rs0, s1 = rs1;
        s0 += __shfl_xor_sync(0xffffffffu, s0, 1);
        s0 += __shfl_xor_sync(0xffffffffu, s0, 2);
        s1 += __shfl_xor_sync(0xffffffffu, s1, 1);
        s1 += __shfl_xor_sync(0xffffffffu, s1, 2);
        if ((lane & 3) == 0) {
            atomicAdd(&l[wmS * 16 + (lane >> 2)],     s0);
            atomicAdd(&l[wmS * 16 + (lane >> 2) + 8], s1);
        }
    }
    __syncthreads();

    #pragma unroll
    for (int mi = 0; mi < 4; mi++) {
        const int r = mi * 16 + (lane >> 2);
        const float inv0 = 1.f / l[r];
        const float inv1 = 1.f / l[r + 8];
        #pragma unroll
        for (int nj = 0; nj < 8; nj++) {
            const int h = warp * 64 + nj * 8 + 2 * (lane & 3);
            const size_t base = ((size_t)b * SR + q0 + r) * HID + h;
            __nv_bfloat162 p0, p1;
            p0.x = __float2bfloat16(of[mi][nj][0] * inv0);
            p0.y = __float2bfloat16(of[mi][nj][1] * inv0);
            p1.x = __float2bfloat16(of[mi][nj][2] * inv1);
            p1.y = __float2bfloat16(of[mi][nj][3] * inv1);
            *(__nv_bfloat162*)&g_o[base]           = p0;
            *(__nv_bfloat162*)&g_o[base + 8 * HID] = p1;
        }
    }
}

// ---------------- LayerNorm over 400 dims (one warp per row) ----------------
__global__ __launch_bounds__(256) void ln_kernel(
    const float* __restrict__ x, const float* __restrict__ gamma,
    const float* __restrict__ beta, float* __restrict__ out)
{
    const int warp = threadIdx.x >> 5, lane = threadIdx.x & 31;
    const size_t row = (size_t)blockIdx.x * 8 + warp;
    const float* xr = x + row * DIN;
    float v[13], s = 0.f, s2 = 0.f;
    #pragma unroll
    for (int i = 0; i < 13; i++) {
        const int idx = lane + 32 * i;
        float val = (idx < DIN) ? xr[idx] : 0.f;
        v[i] = val; s += val; s2 += val * val;
    }
    #pragma unroll
    for (int off = 16; off; off >>= 1) {
        s  += __shfl_xor_sync(0xffffffffu, s,  off);
        s2 += __shfl_xor_sync(0xffffffffu, s2, off);
    }
    const float mu   = s * (1.f / DIN);
    const float var  = s2 * (1.f / DIN) - mu * mu;
    const float rstd = rsqrtf(var + 1e-5f);
    float* orow = out + row * DIN;
    #pragma unroll
    for (int i = 0; i < 13; i++) {
        const int idx = lane + 32 * i;
        if (idx < DIN) orow[idx] = (v[i] - mu) * rstd * gamma[idx] + beta[idx];
    }
}

// ---------------- launch ----------------
extern "C" void kernel_launch(void* const* d_in, const int* in_sizes, int n_in,
                              void* d_out, int out_size)
{
    const float* rgb   = (const float*)d_in[0];
    const float* pose  = (const float*)d_in[1];
    const float* Wq    = (const float*)d_in[2];
    const float* bq    = (const float*)d_in[3];
    const float* Wk    = (const float*)d_in[4];
    const float* bk    = (const float*)d_in[5];
    const float* Wv    = (const float*)d_in[6];
    const float* bv    = (const float*)d_in[7];
    const float* Wp    = (const float*)d_in[8];
    const float* bp    = (const float*)d_in[9];
    const float* gamma = (const float*)d_in[10];
    const float* beta  = (const float*)d_in[11];
    const float* gate  = (const float*)d_in[12];

    void *pq, *pk, *pv, *po, *px, *par, *pap, *pwq, *pwk, *pwv, *pwp;
    cudaGetSymbolAddress(&pq,  g_q);
    cudaGetSymbolAddress(&pk,  g_k);
    cudaGetSymbolAddress(&pv,  g_v);
    cudaGetSymbolAddress(&po,  g_o);
    cudaGetSymbolAddress(&px,  g_x);
    cudaGetSymbolAddress(&par, g_ar);
    cudaGetSymbolAddress(&pap, g_ap);
    cudaGetSymbolAddress(&pwq, g_wq);
    cudaGetSymbolAddress(&pwk, g_wk);
    cudaGetSymbolAddress(&pwv, g_wv);
    cudaGetSymbolAddress(&pwp, g_wp);

    const int M = NB * SR;    // 65536

    // --- conversions (3 launches) ---
    cvt_act<<<2048, 256>>>(rgb,  (bf16*)par, M);
    cvt_act<<<2048, 256>>>(pose, (bf16*)pap, M);
    cvt_w_all<<<dim3((HID*KPAD + 255)/256, 4), 256>>>(Wq, Wk, Wv, Wp,
        (bf16*)pwq, (bf16*)pwk, (bf16*)pwv, (bf16*)pwp);

    // --- GEMMs: 3-stage pipeline, occ 2 ---
    const int smem3 = 3 * G_STG * 2;    // 82944 B
    cudaFuncSetAttribute(gemm3_kernel<0>, cudaFuncAttributeMaxDynamicSharedMemorySize, smem3);
    cudaFuncSetAttribute(gemm3_kernel<1>, cudaFuncAttributeMaxDynamicSharedMemorySize, smem3);

    dim3 blk(256);
    dim3 gq(HID / 64, M / 128);
    gemm3_kernel<0><<<gq, blk, smem3>>>((const bf16*)par, KPAD, KPAD/64,
        (const bf16*)pwq, bq, nullptr, nullptr, pq, HID, HID);
    gemm3_kernel<0><<<gq, blk, smem3>>>((const bf16*)pap, KPAD, KPAD/64,
        (const bf16*)pwk, bk, nullptr, nullptr, pk, HID, HID);
    gemm3_kernel<0><<<gq, blk, smem3>>>((const bf16*)pap, KPAD, KPAD/64,
        (const bf16*)pwv, bv, nullptr, nullptr, pv, HID, HID);

    // --- attention ---
    cudaFuncSetAttribute(attn_kernel, cudaFuncAttributeMaxDynamicSharedMemorySize, SMEM_ATTN);
    attn_kernel<<<dim3(SR / 64, NB), blk, SMEM_ATTN>>>();

    // --- projection + gated residual ---
    dim3 gp(KPAD / 64, M / 128);
    gemm3_kernel<1><<<gp, blk, smem3>>>((const bf16*)po, HID, HID/64,
        (const bf16*)pwp, bp, rgb, gate, px, DIN, DIN);

    // --- layernorm ---
    ln_kernel<<<M / 8, blk>>>((const float*)px, gamma, beta, (float*)d_out);
}